// round 14
// baseline (speedup 1.0000x reference)
#include <cuda_runtime.h>
#include <cuda_fp16.h>
#include <stdint.h>

#define BATCH 4
#define T_SEQ 2048
#define C_EMB 1024
#define NH 16
#define HD 64
#define C3 (3 * C_EMB)
#define M_ROWS (BATCH * T_SEQ)

// Scratch: __device__ globals (runtime allocation is forbidden).
__device__ __half g_qkv_h[(size_t)M_ROWS * C3];   // fp16 qkv
__device__ __half g_y_h[(size_t)M_ROWS * C_EMB];  // fp16 attention output
__device__ __half g_xh[(size_t)M_ROWS * C_EMB];   // fp16 x
__device__ __half g_wah[(size_t)C_EMB * C3];      // fp16 W_attn
__device__ __half g_wph[(size_t)C_EMB * C_EMB];   // fp16 W_proj

// ===========================================================================
// helpers
// ===========================================================================
__device__ __forceinline__ uint32_t smem_u32(const void* p) {
    uint32_t a;
    asm("{ .reg .u64 t; cvta.to.shared.u64 t, %1; cvt.u32.u64 %0, t; }"
        : "=r"(a) : "l"(p));
    return a;
}

#define CP_ASYNC16(dst_u32, src_ptr) \
    asm volatile("cp.async.cg.shared.global [%0], [%1], 16;" \
        :: "r"(dst_u32), "l"(src_ptr) : "memory")
#define CP_COMMIT() asm volatile("cp.async.commit_group;" ::: "memory")
#define CP_WAIT(n)  asm volatile("cp.async.wait_group %0;" :: "n"(n) : "memory")

__device__ __forceinline__ void ldsm_x4(uint32_t* r, uint32_t addr) {
    asm volatile("ldmatrix.sync.aligned.m8n8.x4.shared.b16 {%0,%1,%2,%3}, [%4];"
        : "=r"(r[0]), "=r"(r[1]), "=r"(r[2]), "=r"(r[3]) : "r"(addr));
}
__device__ __forceinline__ void ldsm_x4_t(uint32_t* r, uint32_t addr) {
    asm volatile("ldmatrix.sync.aligned.m8n8.x4.trans.shared.b16 {%0,%1,%2,%3}, [%4];"
        : "=r"(r[0]), "=r"(r[1]), "=r"(r[2]), "=r"(r[3]) : "r"(addr));
}

__device__ __forceinline__ void mma_f16(float* d, const uint32_t* a, const uint32_t* b) {
    asm volatile(
        "mma.sync.aligned.m16n8k16.row.col.f32.f16.f16.f32 "
        "{%0,%1,%2,%3}, {%4,%5,%6,%7}, {%8,%9}, {%0,%1,%2,%3};"
        : "+f"(d[0]), "+f"(d[1]), "+f"(d[2]), "+f"(d[3])
        : "r"(a[0]), "r"(a[1]), "r"(a[2]), "r"(a[3]), "r"(b[0]), "r"(b[1]));
}

__device__ __forceinline__ uint32_t packh2(float lo, float hi) {
    __half2 h = __halves2half2(__float2half_rn(lo), __float2half_rn(hi));
    return *(uint32_t*)&h;
}

// ===========================================================================
// fp32 -> fp16 convert pass (RN)
// ===========================================================================
__global__ __launch_bounds__(256) void f32_to_f16_kernel(
    const float4* __restrict__ src, __half2* __restrict__ dst, int n4)
{
    int i = blockIdx.x * blockDim.x + threadIdx.x;
    if (i < n4) {
        float4 v = src[i];
        dst[2 * i]     = __halves2half2(__float2half_rn(v.x), __float2half_rn(v.y));
        dst[2 * i + 1] = __halves2half2(__float2half_rn(v.z), __float2half_rn(v.w));
    }
}

// ===========================================================================
// FP16 mma.sync GEMM: C[M,N] = A[M,K] @ B[K,N] + bias[N] (fp32 accum)
// BM=256, BN=128, BK=64 halves, 256 threads, 8 warps (4M x 2N),
// warp tile 64x64 -> fragment smem traffic 0.0625 B/FMA (vs 0.094 at 32x64):
// the R13 profile showed the 128 B/cyc/SM crossbar as the binding wall.
// 3-stage cp.async ring, ONE barrier per K-tile (matters at 8 warps/SM).
// ===========================================================================
#define BM 256
#define BN 128
#define BKH 64
#define A_BUF_B (BM * 144)             // 36864
#define B_BUF_B (BKH * 272)            // 17408
#define STAGE_B (A_BUF_B + B_BUF_B)    // 54272
#define GEMM_SMEM_BYTES (3 * STAGE_B)  // 162816

__global__ __launch_bounds__(256, 1) void gemm_f16_kernel(
    const __half* __restrict__ A, const __half* __restrict__ B,
    const float* __restrict__ bias, void* __restrict__ Cout,
    int M, int N, int K, int halfOut)
{
    extern __shared__ char smc[];
    const uint32_t sm_u = smem_u32(smc);

    const int tid  = threadIdx.x;
    const int wid  = tid >> 5;
    const int lane = tid & 31;
    const int g    = lane >> 2;
    const int tg   = lane & 3;
    const int q8   = lane >> 3;
    const int r8   = lane & 7;
    const int warpM = (wid & 3) * 64;       // 4 warps along M
    const int warpN = (wid >> 2) * 64;      // 2 warps along N
    const int rowBase = blockIdx.y * BM;
    const int colBase = blockIdx.x * BN;
    const int NT = K / BKH;

    // lane-constant ldmatrix offsets (bytes within a stage)
    const uint32_t aLane = (uint32_t)((warpM + r8 + (q8 & 1) * 8) * 144 + (q8 >> 1) * 16);
    const uint32_t bLane = (uint32_t)(A_BUF_B + (r8 + (q8 & 1) * 8) * 272
                                      + (warpN + (q8 >> 1) * 8) * 2);

    auto issue_tile = [&](int kt, int buf) {
        const __half* Ap = A + (size_t)rowBase * K + kt * BKH;
        uint32_t sb = sm_u + buf * STAGE_B;
        #pragma unroll
        for (int i = 0; i < 8; i++) {
            int f = tid + 256 * i;          // 2048 chunks: 256 rows x 8
            int r = f >> 3, c = f & 7;
            CP_ASYNC16(sb + (uint32_t)(r * 144 + c * 16), Ap + (size_t)r * K + c * 8);
        }
        const __half* Bp = B + (size_t)(kt * BKH) * N + colBase;
        uint32_t bb = sb + A_BUF_B;
        #pragma unroll
        for (int i = 0; i < 4; i++) {
            int f = tid + 256 * i;          // 1024 chunks: 64 rows x 16
            int k = f >> 4, c = f & 15;
            CP_ASYNC16(bb + (uint32_t)(k * 272 + c * 16), Bp + (size_t)k * N + c * 8);
        }
        CP_COMMIT();
    };

    float acc[4][8][4];
    #pragma unroll
    for (int mt = 0; mt < 4; mt++)
        #pragma unroll
        for (int nt = 0; nt < 8; nt++)
            #pragma unroll
            for (int e = 0; e < 4; e++) acc[mt][nt][e] = 0.0f;

    issue_tile(0, 0);
    issue_tile(1, 1);

    int buf = 0;
    for (int kt = 0; kt < NT; kt++) {
        if (kt + 1 < NT) CP_WAIT(1); else CP_WAIT(0);
        __syncthreads();                  // tile kt visible; tile kt-1 compute done
        if (kt + 2 < NT) {
            int nb = buf + 2; if (nb >= 3) nb -= 3;   // = stage of tile kt-1
            issue_tile(kt + 2, nb);
        }

        uint32_t sb = sm_u + buf * STAGE_B;

        #pragma unroll
        for (int ks = 0; ks < 4; ks++) {      // 4 k-steps of 16 halves
            uint32_t af[4][4], bf[8][2];
            #pragma unroll
            for (int mt = 0; mt < 4; mt++)
                ldsm_x4(af[mt], sb + aLane + (uint32_t)(mt * (16 * 144) + ks * 32));
            #pragma unroll
            for (int j = 0; j < 4; j++) {
                uint32_t t[4];
                ldsm_x4_t(t, sb + bLane + (uint32_t)(ks * (16 * 272) + j * 32));
                bf[2 * j][0] = t[0]; bf[2 * j][1] = t[1];
                bf[2 * j + 1][0] = t[2]; bf[2 * j + 1][1] = t[3];
            }
            #pragma unroll
            for (int mt = 0; mt < 4; mt++)
                #pragma unroll
                for (int nt = 0; nt < 8; nt++)
                    mma_f16(acc[mt][nt], af[mt], bf[nt]);
        }

        if (++buf == 3) buf = 0;
    }

    #pragma unroll
    for (int mt = 0; mt < 4; mt++) {
        #pragma unroll
        for (int nt = 0; nt < 8; nt++) {
            int col = colBase + warpN + nt * 8 + 2 * tg;
            float2 bb = *(const float2*)&bias[col];
            int row0 = rowBase + warpM + mt * 16 + g;
            float v0x = acc[mt][nt][0] + bb.x, v0y = acc[mt][nt][1] + bb.y;
            float v1x = acc[mt][nt][2] + bb.x, v1y = acc[mt][nt][3] + bb.y;
            if (halfOut) {
                __half2* C = (__half2*)Cout;
                C[((size_t)row0 * N + col) >> 1] =
                    __halves2half2(__float2half_rn(v0x), __float2half_rn(v0y));
                C[((size_t)(row0 + 8) * N + col) >> 1] =
                    __halves2half2(__float2half_rn(v1x), __float2half_rn(v1y));
            } else {
                float* C = (float*)Cout;
                float2 v0 = { v0x, v0y }, v1 = { v1x, v1y };
                *(float2*)&C[(size_t)row0 * N + col] = v0;
                *(float2*)&C[(size_t)(row0 + 8) * N + col] = v1;
            }
        }
    }
}

// ===========================================================================
// Flash attention (causal) on fp16 mma.m16n8k16 (unchanged from R13).
// ===========================================================================
#define SM_K0 0
#define SM_V0 9216
#define SM_KV_STAGE 18432
#define SM_Q  36864
#define ATT_SMEM_BYTES (SM_Q + 128 * 144)    // 55296

__global__ __launch_bounds__(256, 2) void attn_f16_kernel(
    const __half* __restrict__ qkv, __half* __restrict__ y)
{
    extern __shared__ char smc[];
    const uint32_t sm32 = smem_u32(smc);

    const int qt = (gridDim.x - 1) - blockIdx.x;   // big tiles first
    const int h  = blockIdx.y;
    const int b  = blockIdx.z;
    const int tid  = threadIdx.x;
    const int wid  = tid >> 5;
    const int lane = tid & 31;
    const int g    = lane >> 2;
    const int tg   = lane & 3;
    const int q8   = lane >> 3;
    const int r8   = lane & 7;
    const int qrow0 = qt * 128;
    const int rw    = wid * 16;

    // ---- stage Q tile (half, coalesced uint4), then read A-fragments
    {
        const __half* qg = qkv + (size_t)(b * T_SEQ + qrow0) * C3 + h * HD;
        #pragma unroll
        for (int i = 0; i < 4; i++) {
            int f = tid + 256 * i;           // 1024 chunks: 128 rows x 8
            int row = f >> 3, c = f & 7;
            *(uint4*)(smc + SM_Q + row * 144 + c * 16) =
                *(const uint4*)(qg + (size_t)row * C3 + c * 8);
        }
    }
    __syncthreads();
    uint32_t qf[4][4];
    {
        const char* Qb = smc + SM_Q + (rw + g) * 144;
        #pragma unroll
        for (int ks = 0; ks < 4; ks++) {
            qf[ks][0] = *(const uint32_t*)(Qb + ks * 32 + tg * 4);
            qf[ks][1] = *(const uint32_t*)(Qb + 8 * 144 + ks * 32 + tg * 4);
            qf[ks][2] = *(const uint32_t*)(Qb + ks * 32 + tg * 4 + 16);
            qf[ks][3] = *(const uint32_t*)(Qb + 8 * 144 + ks * 32 + tg * 4 + 16);
        }
    }

    float o[8][4];
    #pragma unroll
    for (int nt = 0; nt < 8; nt++)
        #pragma unroll
        for (int e = 0; e < 4; e++) o[nt][e] = 0.0f;
    float m0 = -1e30f, m1 = -1e30f, l0 = 0.0f, l1 = 0.0f;
    const float scale = 0.125f;

    const int KT = 2 * qt + 2;
    const uint32_t vLane = (uint32_t)((r8 + (q8 & 1) * 8) * 144 + (q8 >> 1) * 16);

    auto issue = [&](int kt, int buf) {
        const __half* kb = qkv + (size_t)(b * T_SEQ + kt * 64) * C3 + C_EMB + h * HD;
        const __half* vb = kb + C_EMB;
        uint32_t kdst = sm32 + buf * SM_KV_STAGE;
        uint32_t vdst = kdst + SM_V0;
        #pragma unroll
        for (int i = 0; i < 2; i++) {
            int f = tid + 256 * i;           // 512 chunks: 64 rows x 8
            int row = f >> 3, c = f & 7;
            CP_ASYNC16(kdst + (uint32_t)(row * 144 + c * 16), kb + (size_t)row * C3 + c * 8);
        }
        #pragma unroll
        for (int i = 0; i < 2; i++) {
            int f = tid + 256 * i;
            int row = f >> 3, c = f & 7;
            CP_ASYNC16(vdst + (uint32_t)(row * 144 + c * 16), vb + (size_t)row * C3 + c * 8);
        }
        CP_COMMIT();
    };

    issue(0, 0);
    for (int kt = 0; kt < KT; kt++) {
        if (kt + 1 < KT) { issue(kt + 1, (kt + 1) & 1); CP_WAIT(1); }
        else             { CP_WAIT(0); }
        __syncthreads();

        const char* Kb = smc + (kt & 1) * SM_KV_STAGE;
        const uint32_t vBase = sm32 + (kt & 1) * SM_KV_STAGE + SM_V0;

        bool alive = (kt * 64) <= (qrow0 + rw + 15);   // warp-uniform
        if (alive) {
            // ---- S = Q K^T  (16x64 per warp)
            float sa[8][4];
            #pragma unroll
            for (int nt = 0; nt < 8; nt++)
                #pragma unroll
                for (int e = 0; e < 4; e++) sa[nt][e] = 0.0f;
            #pragma unroll
            for (int ks = 0; ks < 4; ks++) {
                #pragma unroll
                for (int nt = 0; nt < 8; nt++) {
                    uint32_t bf[2];
                    const char* kp = Kb + (nt * 8 + g) * 144 + ks * 32 + tg * 4;
                    bf[0] = *(const uint32_t*)(kp);
                    bf[1] = *(const uint32_t*)(kp + 16);
                    mma_f16(sa[nt], qf[ks], bf);
                }
            }

            // ---- mask + online softmax (rows g and g+8)
            bool band = (kt * 64 + 63) > (qrow0 + rw);
            int grow0 = qrow0 + rw + g;
            int gcol0 = kt * 64 + 2 * tg;
            float mx0 = m0, mx1 = m1;
            #pragma unroll
            for (int nt = 0; nt < 8; nt++) {
                int c0 = gcol0 + nt * 8;
                float v0 = sa[nt][0] * scale;
                float v1 = sa[nt][1] * scale;
                float v2 = sa[nt][2] * scale;
                float v3 = sa[nt][3] * scale;
                if (band) {
                    if (c0     > grow0)     v0 = -1e30f;
                    if (c0 + 1 > grow0)     v1 = -1e30f;
                    if (c0     > grow0 + 8) v2 = -1e30f;
                    if (c0 + 1 > grow0 + 8) v3 = -1e30f;
                }
                sa[nt][0] = v0; sa[nt][1] = v1; sa[nt][2] = v2; sa[nt][3] = v3;
                mx0 = fmaxf(mx0, fmaxf(v0, v1));
                mx1 = fmaxf(mx1, fmaxf(v2, v3));
            }
            mx0 = fmaxf(mx0, __shfl_xor_sync(0xffffffffu, mx0, 1));
            mx0 = fmaxf(mx0, __shfl_xor_sync(0xffffffffu, mx0, 2));
            mx1 = fmaxf(mx1, __shfl_xor_sync(0xffffffffu, mx1, 1));
            mx1 = fmaxf(mx1, __shfl_xor_sync(0xffffffffu, mx1, 2));
            float corr0 = __expf(m0 - mx0);
            float corr1 = __expf(m1 - mx1);
            m0 = mx0; m1 = mx1;

            float ls0 = 0.0f, ls1 = 0.0f;
            #pragma unroll
            for (int nt = 0; nt < 8; nt++) {
                float p0 = __expf(sa[nt][0] - m0);
                float p1 = __expf(sa[nt][1] - m0);
                float p2 = __expf(sa[nt][2] - m1);
                float p3 = __expf(sa[nt][3] - m1);
                sa[nt][0] = p0; sa[nt][1] = p1; sa[nt][2] = p2; sa[nt][3] = p3;
                ls0 += p0 + p1;
                ls1 += p2 + p3;
            }
            l0 = l0 * corr0 + ls0;            // lane-partial; reduced at end
            l1 = l1 * corr1 + ls1;
            #pragma unroll
            for (int nt = 0; nt < 8; nt++) {
                o[nt][0] *= corr0; o[nt][1] *= corr0;
                o[nt][2] *= corr1; o[nt][3] *= corr1;
            }

            // ---- P register->register pack (S accum frag == A frag layout)
            uint32_t ph[8][2];
            #pragma unroll
            for (int nt = 0; nt < 8; nt++) {
                ph[nt][0] = packh2(sa[nt][0], sa[nt][1]);
                ph[nt][1] = packh2(sa[nt][2], sa[nt][3]);
            }

            // ---- O += P V  (V frags via ldmatrix.trans)
            #pragma unroll
            for (int ks = 0; ks < 4; ks++) {
                uint32_t pf[4] = { ph[2 * ks][0], ph[2 * ks][1],
                                   ph[2 * ks + 1][0], ph[2 * ks + 1][1] };
                #pragma unroll
                for (int j = 0; j < 4; j++) {
                    uint32_t t[4];
                    ldsm_x4_t(t, vBase + vLane + (uint32_t)(ks * (16 * 144) + j * 32));
                    uint32_t bA[2] = { t[0], t[1] };
                    uint32_t bB[2] = { t[2], t[3] };
                    mma_f16(o[2 * j], pf, bA);
                    mma_f16(o[2 * j + 1], pf, bB);
                }
            }
        }
        __syncthreads();   // all warps done with K/V buffer before reuse
    }

    // ---- final l reduction + normalize + write y (fp16 for proj GEMM)
    l0 += __shfl_xor_sync(0xffffffffu, l0, 1);
    l0 += __shfl_xor_sync(0xffffffffu, l0, 2);
    l1 += __shfl_xor_sync(0xffffffffu, l1, 1);
    l1 += __shfl_xor_sync(0xffffffffu, l1, 2);
    float inv0 = 1.0f / l0;
    float inv1 = 1.0f / l1;

    int row0 = b * T_SEQ + qrow0 + rw + g;
    __half2* Y = (__half2*)y;
    #pragma unroll
    for (int nt = 0; nt < 8; nt++) {
        int col = h * HD + nt * 8 + 2 * tg;
        Y[((size_t)row0 * C_EMB + col) >> 1] =
            __halves2half2(__float2half_rn(o[nt][0] * inv0), __float2half_rn(o[nt][1] * inv0));
        Y[((size_t)(row0 + 8) * C_EMB + col) >> 1] =
            __halves2half2(__float2half_rn(o[nt][2] * inv1), __float2half_rn(o[nt][3] * inv1));
    }
}

// ===========================================================================
extern "C" void kernel_launch(void* const* d_in, const int* in_sizes, int n_in,
                              void* d_out, int out_size)
{
    const float* x      = (const float*)d_in[0];
    const float* W_attn = (const float*)d_in[1];
    const float* b_attn = (const float*)d_in[2];
    const float* W_proj = (const float*)d_in[3];
    const float* b_proj = (const float*)d_in[4];
    float* out = (float*)d_out;

    __half *qkv, *yb, *xh, *wah, *wph;
    cudaGetSymbolAddress((void**)&qkv, g_qkv_h);
    cudaGetSymbolAddress((void**)&yb,  g_y_h);
    cudaGetSymbolAddress((void**)&xh,  g_xh);
    cudaGetSymbolAddress((void**)&wah, g_wah);
    cudaGetSymbolAddress((void**)&wph, g_wph);

    cudaFuncSetAttribute(gemm_f16_kernel,
                         cudaFuncAttributeMaxDynamicSharedMemorySize, GEMM_SMEM_BYTES);
    cudaFuncSetAttribute(attn_f16_kernel,
                         cudaFuncAttributeMaxDynamicSharedMemorySize, ATT_SMEM_BYTES);

    // 0) convert inputs to fp16 (RN) once
    {
        int n4x = (M_ROWS * C_EMB) / 4;
        int n4a = (C_EMB * C3) / 4;
        int n4p = (C_EMB * C_EMB) / 4;
        f32_to_f16_kernel<<<n4x / 256, 256>>>((const float4*)x, (__half2*)xh, n4x);
        f32_to_f16_kernel<<<n4a / 256, 256>>>((const float4*)W_attn, (__half2*)wah, n4a);
        f32_to_f16_kernel<<<n4p / 256, 256>>>((const float4*)W_proj, (__half2*)wph, n4p);
    }

    // 1) qkv = x_h @ Wa_h + b_attn   (fp32 accum, fp16 output)
    gemm_f16_kernel<<<dim3(C3 / BN, M_ROWS / BM), 256, GEMM_SMEM_BYTES>>>(
        xh, wah, b_attn, qkv, M_ROWS, C3, C_EMB, 1);

    // 2) causal flash attention -> y (fp16)
    attn_f16_kernel<<<dim3(T_SEQ / 128, NH, BATCH), 256, ATT_SMEM_BYTES>>>(qkv, yb);

    // 3) out = y @ Wp_h + b_proj  (fp32 output, not rounded)
    gemm_f16_kernel<<<dim3(C_EMB / BN, M_ROWS / BM), 256, GEMM_SMEM_BYTES>>>(
        yb, wph, b_proj, out, M_ROWS, C_EMB, C_EMB, 0);
}

// round 15
// speedup vs baseline: 1.0976x; 1.0976x over previous
#include <cuda_runtime.h>
#include <cuda_fp16.h>
#include <stdint.h>

#define BATCH 4
#define T_SEQ 2048
#define C_EMB 1024
#define NH 16
#define HD 64
#define C3 (3 * C_EMB)
#define M_ROWS (BATCH * T_SEQ)

// Scratch: __device__ globals (runtime allocation is forbidden).
__device__ __half g_qkv_h[(size_t)M_ROWS * C3];   // fp16 qkv
__device__ __half g_y_h[(size_t)M_ROWS * C_EMB];  // fp16 attention output
__device__ __half g_xh[(size_t)M_ROWS * C_EMB];   // fp16 x
__device__ __half g_wah[(size_t)C_EMB * C3];      // fp16 W_attn
__device__ __half g_wph[(size_t)C_EMB * C_EMB];   // fp16 W_proj

// ===========================================================================
// helpers
// ===========================================================================
__device__ __forceinline__ uint32_t smem_u32(const void* p) {
    uint32_t a;
    asm("{ .reg .u64 t; cvta.to.shared.u64 t, %1; cvt.u32.u64 %0, t; }"
        : "=r"(a) : "l"(p));
    return a;
}

#define CP_ASYNC16(dst_u32, src_ptr) \
    asm volatile("cp.async.cg.shared.global [%0], [%1], 16;" \
        :: "r"(dst_u32), "l"(src_ptr) : "memory")
#define CP_COMMIT() asm volatile("cp.async.commit_group;" ::: "memory")
#define CP_WAIT(n)  asm volatile("cp.async.wait_group %0;" :: "n"(n) : "memory")

__device__ __forceinline__ void ldsm_x4(uint32_t* r, uint32_t addr) {
    asm volatile("ldmatrix.sync.aligned.m8n8.x4.shared.b16 {%0,%1,%2,%3}, [%4];"
        : "=r"(r[0]), "=r"(r[1]), "=r"(r[2]), "=r"(r[3]) : "r"(addr));
}
__device__ __forceinline__ void ldsm_x4_t(uint32_t* r, uint32_t addr) {
    asm volatile("ldmatrix.sync.aligned.m8n8.x4.trans.shared.b16 {%0,%1,%2,%3}, [%4];"
        : "=r"(r[0]), "=r"(r[1]), "=r"(r[2]), "=r"(r[3]) : "r"(addr));
}

__device__ __forceinline__ void mma_f16(float* d, const uint32_t* a, const uint32_t* b) {
    asm volatile(
        "mma.sync.aligned.m16n8k16.row.col.f32.f16.f16.f32 "
        "{%0,%1,%2,%3}, {%4,%5,%6,%7}, {%8,%9}, {%0,%1,%2,%3};"
        : "+f"(d[0]), "+f"(d[1]), "+f"(d[2]), "+f"(d[3])
        : "r"(a[0]), "r"(a[1]), "r"(a[2]), "r"(a[3]), "r"(b[0]), "r"(b[1]));
}

__device__ __forceinline__ uint32_t packh2(float lo, float hi) {
    __half2 h = __halves2half2(__float2half_rn(lo), __float2half_rn(hi));
    return *(uint32_t*)&h;
}

// ===========================================================================
// fp32 -> fp16 convert pass (RN)
// ===========================================================================
__global__ __launch_bounds__(256) void f32_to_f16_kernel(
    const float4* __restrict__ src, __half2* __restrict__ dst, int n4)
{
    int i = blockIdx.x * blockDim.x + threadIdx.x;
    if (i < n4) {
        float4 v = src[i];
        dst[2 * i]     = __halves2half2(__float2half_rn(v.x), __float2half_rn(v.y));
        dst[2 * i + 1] = __halves2half2(__float2half_rn(v.z), __float2half_rn(v.w));
    }
}

// ===========================================================================
// FP16 mma.sync GEMM (R13 shape): BM=BN=128, BK=64, 256 thr, warp 32x64,
// regs=128 -> 2 CTAs/SM. NEW: 3-stage cp.async ring, ONE barrier per K-tile.
// ===========================================================================
#define BM 128
#define BN 128
#define BKH 64
#define A_BUF_B (BM * 144)             // 18432
#define B_BUF_B (BKH * 272)            // 17408
#define STAGE_B (A_BUF_B + B_BUF_B)    // 35840
#define GEMM_SMEM_BYTES (3 * STAGE_B)  // 107520 (x2 CTAs = 210 KB <= 228)

__global__ __launch_bounds__(256, 2) void gemm_f16_kernel(
    const __half* __restrict__ A, const __half* __restrict__ B,
    const float* __restrict__ bias, void* __restrict__ Cout,
    int M, int N, int K, int halfOut)
{
    extern __shared__ char smc[];
    const uint32_t sm_u = smem_u32(smc);

    const int tid  = threadIdx.x;
    const int wid  = tid >> 5;
    const int lane = tid & 31;
    const int g    = lane >> 2;
    const int tg   = lane & 3;
    const int q8   = lane >> 3;
    const int r8   = lane & 7;
    const int warpM = (wid & 3) * 32;
    const int warpN = (wid >> 2) * 64;
    const int rowBase = blockIdx.y * BM;
    const int colBase = blockIdx.x * BN;
    const int NT = K / BKH;

    const uint32_t aLane = (uint32_t)((warpM + r8 + (q8 & 1) * 8) * 144 + (q8 >> 1) * 16);
    const uint32_t bLane = (uint32_t)(A_BUF_B + (r8 + (q8 & 1) * 8) * 272
                                      + (warpN + (q8 >> 1) * 8) * 2);

    auto issue_tile = [&](int kt, int buf) {
        const __half* Ap = A + (size_t)rowBase * K + kt * BKH;
        uint32_t sb = sm_u + buf * STAGE_B;
        #pragma unroll
        for (int i = 0; i < 4; i++) {
            int f = tid + 256 * i;          // 1024 chunks: 128 rows x 8
            int r = f >> 3, c = f & 7;
            CP_ASYNC16(sb + (uint32_t)(r * 144 + c * 16), Ap + (size_t)r * K + c * 8);
        }
        const __half* Bp = B + (size_t)(kt * BKH) * N + colBase;
        uint32_t bb = sb + A_BUF_B;
        #pragma unroll
        for (int i = 0; i < 4; i++) {
            int f = tid + 256 * i;          // 1024 chunks: 64 rows x 16
            int k = f >> 4, c = f & 15;
            CP_ASYNC16(bb + (uint32_t)(k * 272 + c * 16), Bp + (size_t)k * N + c * 8);
        }
        CP_COMMIT();
    };

    float acc[2][8][4];
    #pragma unroll
    for (int mt = 0; mt < 2; mt++)
        #pragma unroll
        for (int nt = 0; nt < 8; nt++)
            #pragma unroll
            for (int e = 0; e < 4; e++) acc[mt][nt][e] = 0.0f;

    issue_tile(0, 0);
    issue_tile(1, 1);

    int buf = 0;
    for (int kt = 0; kt < NT; kt++) {
        if (kt + 1 < NT) CP_WAIT(1); else CP_WAIT(0);
        __syncthreads();                 // tile kt visible; tile kt-1 compute done
        if (kt + 2 < NT) {
            int nb = buf + 2; if (nb >= 3) nb -= 3;   // stage of tile kt-1 (free)
            issue_tile(kt + 2, nb);
        }

        uint32_t sb = sm_u + buf * STAGE_B;

        #pragma unroll
        for (int ks = 0; ks < 4; ks++) {      // 4 k-steps of 16 halves
            uint32_t af[2][4], bf[8][2];
            #pragma unroll
            for (int mt = 0; mt < 2; mt++)
                ldsm_x4(af[mt], sb + aLane + (uint32_t)(mt * (16 * 144) + ks * 32));
            #pragma unroll
            for (int j = 0; j < 4; j++) {
                uint32_t t[4];
                ldsm_x4_t(t, sb + bLane + (uint32_t)(ks * (16 * 272) + j * 32));
                bf[2 * j][0] = t[0]; bf[2 * j][1] = t[1];
                bf[2 * j + 1][0] = t[2]; bf[2 * j + 1][1] = t[3];
            }
            #pragma unroll
            for (int mt = 0; mt < 2; mt++)
                #pragma unroll
                for (int nt = 0; nt < 8; nt++)
                    mma_f16(acc[mt][nt], af[mt], bf[nt]);
        }

        if (++buf == 3) buf = 0;
    }

    #pragma unroll
    for (int mt = 0; mt < 2; mt++) {
        #pragma unroll
        for (int nt = 0; nt < 8; nt++) {
            int col = colBase + warpN + nt * 8 + 2 * tg;
            float2 bb = *(const float2*)&bias[col];
            int row0 = rowBase + warpM + mt * 16 + g;
            float v0x = acc[mt][nt][0] + bb.x, v0y = acc[mt][nt][1] + bb.y;
            float v1x = acc[mt][nt][2] + bb.x, v1y = acc[mt][nt][3] + bb.y;
            if (halfOut) {
                __half2* C = (__half2*)Cout;
                C[((size_t)row0 * N + col) >> 1] =
                    __halves2half2(__float2half_rn(v0x), __float2half_rn(v0y));
                C[((size_t)(row0 + 8) * N + col) >> 1] =
                    __halves2half2(__float2half_rn(v1x), __float2half_rn(v1y));
            } else {
                float* C = (float*)Cout;
                float2 v0 = { v0x, v0y }, v1 = { v1x, v1y };
                *(float2*)&C[(size_t)row0 * N + col] = v0;
                *(float2*)&C[(size_t)(row0 + 8) * N + col] = v1;
            }
        }
    }
}

// ===========================================================================
// Flash attention (causal) fp16 mma. NEW: 3-stage KV ring (ONE barrier per
// KV-tile) + log2-domain softmax (exp2f; saves the per-element EX2-prescale
// FMUL). Everything else identical to R13.
// ===========================================================================
#define SM_V0 9216
#define SM_KV_STAGE 18432
#define SM_Q  (3 * SM_KV_STAGE)              // 55296
#define ATT_SMEM_BYTES (SM_Q + 128 * 144)    // 73728 (x2 CTAs = 144 KB)

__global__ __launch_bounds__(256, 2) void attn_f16_kernel(
    const __half* __restrict__ qkv, __half* __restrict__ y)
{
    extern __shared__ char smc[];
    const uint32_t sm32 = smem_u32(smc);

    const int qt = (gridDim.x - 1) - blockIdx.x;   // big tiles first
    const int h  = blockIdx.y;
    const int b  = blockIdx.z;
    const int tid  = threadIdx.x;
    const int wid  = tid >> 5;
    const int lane = tid & 31;
    const int g    = lane >> 2;
    const int tg   = lane & 3;
    const int q8   = lane >> 3;
    const int r8   = lane & 7;
    const int qrow0 = qt * 128;
    const int rw    = wid * 16;

    // ---- stage Q tile (half, coalesced uint4), then read A-fragments
    {
        const __half* qg = qkv + (size_t)(b * T_SEQ + qrow0) * C3 + h * HD;
        #pragma unroll
        for (int i = 0; i < 4; i++) {
            int f = tid + 256 * i;           // 1024 chunks: 128 rows x 8
            int row = f >> 3, c = f & 7;
            *(uint4*)(smc + SM_Q + row * 144 + c * 16) =
                *(const uint4*)(qg + (size_t)row * C3 + c * 8);
        }
    }
    __syncthreads();
    uint32_t qf[4][4];
    {
        const char* Qb = smc + SM_Q + (rw + g) * 144;
        #pragma unroll
        for (int ks = 0; ks < 4; ks++) {
            qf[ks][0] = *(const uint32_t*)(Qb + ks * 32 + tg * 4);
            qf[ks][1] = *(const uint32_t*)(Qb + 8 * 144 + ks * 32 + tg * 4);
            qf[ks][2] = *(const uint32_t*)(Qb + ks * 32 + tg * 4 + 16);
            qf[ks][3] = *(const uint32_t*)(Qb + 8 * 144 + ks * 32 + tg * 4 + 16);
        }
    }

    float o[8][4];
    #pragma unroll
    for (int nt = 0; nt < 8; nt++)
        #pragma unroll
        for (int e = 0; e < 4; e++) o[nt][e] = 0.0f;
    float m0 = -1e30f, m1 = -1e30f, l0 = 0.0f, l1 = 0.0f;
    const float scl2 = 0.125f * 1.44269504088896340736f;   // scale * log2(e)

    const int KT = 2 * qt + 2;
    const uint32_t vLane = (uint32_t)((r8 + (q8 & 1) * 8) * 144 + (q8 >> 1) * 16);

    auto issue = [&](int kt, int buf) {
        const __half* kb = qkv + (size_t)(b * T_SEQ + kt * 64) * C3 + C_EMB + h * HD;
        const __half* vb = kb + C_EMB;
        uint32_t kdst = sm32 + buf * SM_KV_STAGE;
        uint32_t vdst = kdst + SM_V0;
        #pragma unroll
        for (int i = 0; i < 2; i++) {
            int f = tid + 256 * i;           // 512 chunks: 64 rows x 8
            int row = f >> 3, c = f & 7;
            CP_ASYNC16(kdst + (uint32_t)(row * 144 + c * 16), kb + (size_t)row * C3 + c * 8);
        }
        #pragma unroll
        for (int i = 0; i < 2; i++) {
            int f = tid + 256 * i;
            int row = f >> 3, c = f & 7;
            CP_ASYNC16(vdst + (uint32_t)(row * 144 + c * 16), vb + (size_t)row * C3 + c * 8);
        }
        CP_COMMIT();
    };

    issue(0, 0);
    issue(1, 1);
    int buf = 0;
    for (int kt = 0; kt < KT; kt++) {
        if (kt + 1 < KT) CP_WAIT(1); else CP_WAIT(0);
        __syncthreads();                 // tile kt visible; kt-1 compute done
        if (kt + 2 < KT) {
            int nb = buf + 2; if (nb >= 3) nb -= 3;   // buffer of tile kt-1
            issue(kt + 2, nb);
        }

        const char* Kb = smc + buf * SM_KV_STAGE;
        const uint32_t vBase = sm32 + buf * SM_KV_STAGE + SM_V0;
        if (++buf == 3) buf = 0;

        bool alive = (kt * 64) <= (qrow0 + rw + 15);   // warp-uniform
        if (alive) {
            // ---- S = Q K^T  (16x64 per warp)
            float sa[8][4];
            #pragma unroll
            for (int nt = 0; nt < 8; nt++)
                #pragma unroll
                for (int e = 0; e < 4; e++) sa[nt][e] = 0.0f;
            #pragma unroll
            for (int ks = 0; ks < 4; ks++) {
                #pragma unroll
                for (int nt = 0; nt < 8; nt++) {
                    uint32_t bf[2];
                    const char* kp = Kb + (nt * 8 + g) * 144 + ks * 32 + tg * 4;
                    bf[0] = *(const uint32_t*)(kp);
                    bf[1] = *(const uint32_t*)(kp + 16);
                    mma_f16(sa[nt], qf[ks], bf);
                }
            }

            // ---- mask + online softmax in log2 domain (rows g and g+8)
            bool band = (kt * 64 + 63) > (qrow0 + rw);
            int grow0 = qrow0 + rw + g;
            int gcol0 = kt * 64 + 2 * tg;
            float mx0 = m0, mx1 = m1;
            #pragma unroll
            for (int nt = 0; nt < 8; nt++) {
                int c0 = gcol0 + nt * 8;
                float v0 = sa[nt][0] * scl2;
                float v1 = sa[nt][1] * scl2;
                float v2 = sa[nt][2] * scl2;
                float v3 = sa[nt][3] * scl2;
                if (band) {
                    if (c0     > grow0)     v0 = -1e30f;
                    if (c0 + 1 > grow0)     v1 = -1e30f;
                    if (c0     > grow0 + 8) v2 = -1e30f;
                    if (c0 + 1 > grow0 + 8) v3 = -1e30f;
                }
                sa[nt][0] = v0; sa[nt][1] = v1; sa[nt][2] = v2; sa[nt][3] = v3;
                mx0 = fmaxf(mx0, fmaxf(v0, v1));
                mx1 = fmaxf(mx1, fmaxf(v2, v3));
            }
            mx0 = fmaxf(mx0, __shfl_xor_sync(0xffffffffu, mx0, 1));
            mx0 = fmaxf(mx0, __shfl_xor_sync(0xffffffffu, mx0, 2));
            mx1 = fmaxf(mx1, __shfl_xor_sync(0xffffffffu, mx1, 1));
            mx1 = fmaxf(mx1, __shfl_xor_sync(0xffffffffu, mx1, 2));
            float corr0 = exp2f(m0 - mx0);
            float corr1 = exp2f(m1 - mx1);
            m0 = mx0; m1 = mx1;

            float ls0 = 0.0f, ls1 = 0.0f;
            #pragma unroll
            for (int nt = 0; nt < 8; nt++) {
                float p0 = exp2f(sa[nt][0] - m0);
                float p1 = exp2f(sa[nt][1] - m0);
                float p2 = exp2f(sa[nt][2] - m1);
                float p3 = exp2f(sa[nt][3] - m1);
                sa[nt][0] = p0; sa[nt][1] = p1; sa[nt][2] = p2; sa[nt][3] = p3;
                ls0 += p0 + p1;
                ls1 += p2 + p3;
            }
            l0 = l0 * corr0 + ls0;            // lane-partial; reduced at end
            l1 = l1 * corr1 + ls1;
            #pragma unroll
            for (int nt = 0; nt < 8; nt++) {
                o[nt][0] *= corr0; o[nt][1] *= corr0;
                o[nt][2] *= corr1; o[nt][3] *= corr1;
            }

            // ---- P register->register pack (S accum frag == A frag layout)
            uint32_t ph[8][2];
            #pragma unroll
            for (int nt = 0; nt < 8; nt++) {
                ph[nt][0] = packh2(sa[nt][0], sa[nt][1]);
                ph[nt][1] = packh2(sa[nt][2], sa[nt][3]);
            }

            // ---- O += P V  (V frags via ldmatrix.trans)
            #pragma unroll
            for (int ks = 0; ks < 4; ks++) {
                uint32_t pf[4] = { ph[2 * ks][0], ph[2 * ks][1],
                                   ph[2 * ks + 1][0], ph[2 * ks + 1][1] };
                #pragma unroll
                for (int j = 0; j < 4; j++) {
                    uint32_t t[4];
                    ldsm_x4_t(t, vBase + vLane + (uint32_t)(ks * (16 * 144) + j * 32));
                    uint32_t bA[2] = { t[0], t[1] };
                    uint32_t bB[2] = { t[2], t[3] };
                    mma_f16(o[2 * j], pf, bA);
                    mma_f16(o[2 * j + 1], pf, bB);
                }
            }
        }
    }

    // ---- final l reduction + normalize + write y (fp16 for proj GEMM)
    l0 += __shfl_xor_sync(0xffffffffu, l0, 1);
    l0 += __shfl_xor_sync(0xffffffffu, l0, 2);
    l1 += __shfl_xor_sync(0xffffffffu, l1, 1);
    l1 += __shfl_xor_sync(0xffffffffu, l1, 2);
    float inv0 = 1.0f / l0;
    float inv1 = 1.0f / l1;

    int row0 = b * T_SEQ + qrow0 + rw + g;
    __half2* Y = (__half2*)y;
    #pragma unroll
    for (int nt = 0; nt < 8; nt++) {
        int col = h * HD + nt * 8 + 2 * tg;
        Y[((size_t)row0 * C_EMB + col) >> 1] =
            __halves2half2(__float2half_rn(o[nt][0] * inv0), __float2half_rn(o[nt][1] * inv0));
        Y[((size_t)(row0 + 8) * C_EMB + col) >> 1] =
            __halves2half2(__float2half_rn(o[nt][2] * inv1), __float2half_rn(o[nt][3] * inv1));
    }
}

// ===========================================================================
extern "C" void kernel_launch(void* const* d_in, const int* in_sizes, int n_in,
                              void* d_out, int out_size)
{
    const float* x      = (const float*)d_in[0];
    const float* W_attn = (const float*)d_in[1];
    const float* b_attn = (const float*)d_in[2];
    const float* W_proj = (const float*)d_in[3];
    const float* b_proj = (const float*)d_in[4];
    float* out = (float*)d_out;

    __half *qkv, *yb, *xh, *wah, *wph;
    cudaGetSymbolAddress((void**)&qkv, g_qkv_h);
    cudaGetSymbolAddress((void**)&yb,  g_y_h);
    cudaGetSymbolAddress((void**)&xh,  g_xh);
    cudaGetSymbolAddress((void**)&wah, g_wah);
    cudaGetSymbolAddress((void**)&wph, g_wph);

    cudaFuncSetAttribute(gemm_f16_kernel,
                         cudaFuncAttributeMaxDynamicSharedMemorySize, GEMM_SMEM_BYTES);
    cudaFuncSetAttribute(attn_f16_kernel,
                         cudaFuncAttributeMaxDynamicSharedMemorySize, ATT_SMEM_BYTES);

    // 0) convert inputs to fp16 (RN) once
    {
        int n4x = (M_ROWS * C_EMB) / 4;
        int n4a = (C_EMB * C3) / 4;
        int n4p = (C_EMB * C_EMB) / 4;
        f32_to_f16_kernel<<<n4x / 256, 256>>>((const float4*)x, (__half2*)xh, n4x);
        f32_to_f16_kernel<<<n4a / 256, 256>>>((const float4*)W_attn, (__half2*)wah, n4a);
        f32_to_f16_kernel<<<n4p / 256, 256>>>((const float4*)W_proj, (__half2*)wph, n4p);
    }

    // 1) qkv = x_h @ Wa_h + b_attn   (fp32 accum, fp16 output)
    gemm_f16_kernel<<<dim3(C3 / BN, M_ROWS / BM), 256, GEMM_SMEM_BYTES>>>(
        xh, wah, b_attn, qkv, M_ROWS, C3, C_EMB, 1);

    // 2) causal flash attention -> y (fp16)
    attn_f16_kernel<<<dim3(T_SEQ / 128, NH, BATCH), 256, ATT_SMEM_BYTES>>>(qkv, yb);

    // 3) out = y @ Wp_h + b_proj  (fp32 output, not rounded)
    gemm_f16_kernel<<<dim3(C_EMB / BN, M_ROWS / BM), 256, GEMM_SMEM_BYTES>>>(
        yb, wph, b_proj, out, M_ROWS, C_EMB, C_EMB, 0);
}

// round 17
// speedup vs baseline: 1.1009x; 1.0030x over previous
#include <cuda_runtime.h>
#include <cuda_fp16.h>
#include <stdint.h>

#define BATCH 4
#define T_SEQ 2048
#define C_EMB 1024
#define NH 16
#define HD 64
#define C3 (3 * C_EMB)
#define M_ROWS (BATCH * T_SEQ)

// Scratch: __device__ globals (runtime allocation is forbidden).
__device__ __half g_qkv_h[(size_t)M_ROWS * C3];   // fp16 qkv
__device__ __half g_y_h[(size_t)M_ROWS * C_EMB];  // fp16 attention output
__device__ __half g_xh[(size_t)M_ROWS * C_EMB];   // fp16 x
__device__ __half g_wah[(size_t)C_EMB * C3];      // fp16 W_attn
__device__ __half g_wph[(size_t)C_EMB * C_EMB];   // fp16 W_proj

// ===========================================================================
// helpers
// ===========================================================================
__device__ __forceinline__ uint32_t smem_u32(const void* p) {
    uint32_t a;
    asm("{ .reg .u64 t; cvta.to.shared.u64 t, %1; cvt.u32.u64 %0, t; }"
        : "=r"(a) : "l"(p));
    return a;
}

#define CP_ASYNC16(dst_u32, src_ptr) \
    asm volatile("cp.async.cg.shared.global [%0], [%1], 16;" \
        :: "r"(dst_u32), "l"(src_ptr) : "memory")
#define CP_COMMIT() asm volatile("cp.async.commit_group;" ::: "memory")
#define CP_WAIT(n)  asm volatile("cp.async.wait_group %0;" :: "n"(n) : "memory")

__device__ __forceinline__ void ldsm_x4(uint32_t* r, uint32_t addr) {
    asm volatile("ldmatrix.sync.aligned.m8n8.x4.shared.b16 {%0,%1,%2,%3}, [%4];"
        : "=r"(r[0]), "=r"(r[1]), "=r"(r[2]), "=r"(r[3]) : "r"(addr));
}
__device__ __forceinline__ void ldsm_x4_t(uint32_t* r, uint32_t addr) {
    asm volatile("ldmatrix.sync.aligned.m8n8.x4.trans.shared.b16 {%0,%1,%2,%3}, [%4];"
        : "=r"(r[0]), "=r"(r[1]), "=r"(r[2]), "=r"(r[3]) : "r"(addr));
}

__device__ __forceinline__ void mma_f16(float* d, const uint32_t* a, const uint32_t* b) {
    asm volatile(
        "mma.sync.aligned.m16n8k16.row.col.f32.f16.f16.f32 "
        "{%0,%1,%2,%3}, {%4,%5,%6,%7}, {%8,%9}, {%0,%1,%2,%3};"
        : "+f"(d[0]), "+f"(d[1]), "+f"(d[2]), "+f"(d[3])
        : "r"(a[0]), "r"(a[1]), "r"(a[2]), "r"(a[3]), "r"(b[0]), "r"(b[1]));
}

__device__ __forceinline__ uint32_t packh2(float lo, float hi) {
    __half2 h = __halves2half2(__float2half_rn(lo), __float2half_rn(hi));
    return *(uint32_t*)&h;
}

// ===========================================================================
// fp32 -> fp16 convert pass (RN)
// ===========================================================================
__global__ __launch_bounds__(256) void f32_to_f16_kernel(
    const float4* __restrict__ src, __half2* __restrict__ dst, int n4)
{
    int i = blockIdx.x * blockDim.x + threadIdx.x;
    if (i < n4) {
        float4 v = src[i];
        dst[2 * i]     = __halves2half2(__float2half_rn(v.x), __float2half_rn(v.y));
        dst[2 * i + 1] = __halves2half2(__float2half_rn(v.z), __float2half_rn(v.w));
    }
}

// ===========================================================================
// FP16 mma.sync GEMM: BM=BN=128, BK=64, 256 thr, warp 32x64, 2 CTAs/SM.
// NEW (R16): software-pipelined fragment loads -- each ldmatrix for B-group
// j+1 (and next kstep's A frags, hoisted to the j==2 slot) issues BEFORE the
// mmas of group j, so LSU and tensor overlap instead of phase-oscillating.
// Peak live frag regs unchanged (24): afb 16 + 2 t-groups 8.
// ===========================================================================
#define BM 128
#define BN 128
#define BKH 64
#define A_BUF_B (BM * 144)             // 18432
#define B_BUF_B (BKH * 272)            // 17408
#define STAGE_B (A_BUF_B + B_BUF_B)    // 35840
#define GEMM_SMEM_BYTES (3 * STAGE_B)  // 107520 (x2 CTAs = 210 KB <= 228)

__global__ __launch_bounds__(256, 2) void gemm_f16_kernel(
    const __half* __restrict__ A, const __half* __restrict__ B,
    const float* __restrict__ bias, void* __restrict__ Cout,
    int M, int N, int K, int halfOut)
{
    extern __shared__ char smc[];
    const uint32_t sm_u = smem_u32(smc);

    const int tid  = threadIdx.x;
    const int wid  = tid >> 5;
    const int lane = tid & 31;
    const int g    = lane >> 2;
    const int tg   = lane & 3;
    const int q8   = lane >> 3;
    const int r8   = lane & 7;
    const int warpM = (wid & 3) * 32;
    const int warpN = (wid >> 2) * 64;
    const int rowBase = blockIdx.y * BM;
    const int colBase = blockIdx.x * BN;
    const int NT = K / BKH;

    const uint32_t aLane = (uint32_t)((warpM + r8 + (q8 & 1) * 8) * 144 + (q8 >> 1) * 16);
    const uint32_t bLane = (uint32_t)(A_BUF_B + (r8 + (q8 & 1) * 8) * 272
                                      + (warpN + (q8 >> 1) * 8) * 2);

    auto issue_tile = [&](int kt, int buf) {
        const __half* Ap = A + (size_t)rowBase * K + kt * BKH;
        uint32_t sb = sm_u + buf * STAGE_B;
        #pragma unroll
        for (int i = 0; i < 4; i++) {
            int f = tid + 256 * i;          // 1024 chunks: 128 rows x 8
            int r = f >> 3, c = f & 7;
            CP_ASYNC16(sb + (uint32_t)(r * 144 + c * 16), Ap + (size_t)r * K + c * 8);
        }
        const __half* Bp = B + (size_t)(kt * BKH) * N + colBase;
        uint32_t bb = sb + A_BUF_B;
        #pragma unroll
        for (int i = 0; i < 4; i++) {
            int f = tid + 256 * i;          // 1024 chunks: 64 rows x 16
            int k = f >> 4, c = f & 15;
            CP_ASYNC16(bb + (uint32_t)(k * 272 + c * 16), Bp + (size_t)k * N + c * 8);
        }
        CP_COMMIT();
    };

    float acc[2][8][4];
    #pragma unroll
    for (int mt = 0; mt < 2; mt++)
        #pragma unroll
        for (int nt = 0; nt < 8; nt++)
            #pragma unroll
            for (int e = 0; e < 4; e++) acc[mt][nt][e] = 0.0f;

    issue_tile(0, 0);
    issue_tile(1, 1);

    int buf = 0;
    for (int kt = 0; kt < NT; kt++) {
        if (kt + 1 < NT) CP_WAIT(1); else CP_WAIT(0);
        __syncthreads();                 // tile kt visible; tile kt-1 compute done
        if (kt + 2 < NT) {
            int nb = buf + 2; if (nb >= 3) nb -= 3;   // stage of tile kt-1 (free)
            issue_tile(kt + 2, nb);
        }

        uint32_t sb = sm_u + buf * STAGE_B;

        // ---- software-pipelined fragment/mma loop --------------------------
        uint32_t afb[2][2][4];   // [ks&1][mt][4]
        uint32_t tb[2][4];       // alternating B-groups

        ldsm_x4(afb[0][0], sb + aLane);
        ldsm_x4(afb[0][1], sb + aLane + (uint32_t)(16 * 144));
        ldsm_x4_t(tb[0], sb + bLane);

        #pragma unroll
        for (int ks = 0; ks < 4; ks++) {
            #pragma unroll
            for (int j = 0; j < 4; j++) {
                const int step = ks * 4 + j;
                const int cur = step & 1;
                // prefetch next B-group
                if (step + 1 < 16) {
                    const int nks = (j < 3) ? ks : ks + 1;
                    const int nj  = (j < 3) ? j + 1 : 0;
                    ldsm_x4_t(tb[cur ^ 1],
                              sb + bLane + (uint32_t)(nks * (16 * 272) + nj * 32));
                }
                // prefetch next kstep's A-frags (hoisted before last j)
                if (j == 2 && ks < 3) {
                    ldsm_x4(afb[(ks + 1) & 1][0],
                            sb + aLane + (uint32_t)((ks + 1) * 32));
                    ldsm_x4(afb[(ks + 1) & 1][1],
                            sb + aLane + (uint32_t)(16 * 144 + (ks + 1) * 32));
                }
                // 4 mmas on current B-group
                mma_f16(acc[0][2 * j],     afb[ks & 1][0], tb[cur]);
                mma_f16(acc[0][2 * j + 1], afb[ks & 1][0], tb[cur] + 2);
                mma_f16(acc[1][2 * j],     afb[ks & 1][1], tb[cur]);
                mma_f16(acc[1][2 * j + 1], afb[ks & 1][1], tb[cur] + 2);
            }
        }

        if (++buf == 3) buf = 0;
    }

    #pragma unroll
    for (int mt = 0; mt < 2; mt++) {
        #pragma unroll
        for (int nt = 0; nt < 8; nt++) {
            int col = colBase + warpN + nt * 8 + 2 * tg;
            float2 bb = *(const float2*)&bias[col];
            int row0 = rowBase + warpM + mt * 16 + g;
            float v0x = acc[mt][nt][0] + bb.x, v0y = acc[mt][nt][1] + bb.y;
            float v1x = acc[mt][nt][2] + bb.x, v1y = acc[mt][nt][3] + bb.y;
            if (halfOut) {
                __half2* C = (__half2*)Cout;
                C[((size_t)row0 * N + col) >> 1] =
                    __halves2half2(__float2half_rn(v0x), __float2half_rn(v0y));
                C[((size_t)(row0 + 8) * N + col) >> 1] =
                    __halves2half2(__float2half_rn(v1x), __float2half_rn(v1y));
            } else {
                float* C = (float*)Cout;
                float2 v0 = { v0x, v0y }, v1 = { v1x, v1y };
                *(float2*)&C[(size_t)row0 * N + col] = v0;
                *(float2*)&C[(size_t)(row0 + 8) * N + col] = v1;
            }
        }
    }
}

// ===========================================================================
// Flash attention (causal) fp16 mma (unchanged from R15: 3-stage KV ring,
// one barrier per KV-tile, log2-domain softmax).
// ===========================================================================
#define SM_V0 9216
#define SM_KV_STAGE 18432
#define SM_Q  (3 * SM_KV_STAGE)              // 55296
#define ATT_SMEM_BYTES (SM_Q + 128 * 144)    // 73728 (x2 CTAs = 144 KB)

__global__ __launch_bounds__(256, 2) void attn_f16_kernel(
    const __half* __restrict__ qkv, __half* __restrict__ y)
{
    extern __shared__ char smc[];
    const uint32_t sm32 = smem_u32(smc);

    const int qt = (gridDim.x - 1) - blockIdx.x;   // big tiles first
    const int h  = blockIdx.y;
    const int b  = blockIdx.z;
    const int tid  = threadIdx.x;
    const int wid  = tid >> 5;
    const int lane = tid & 31;
    const int g    = lane >> 2;
    const int tg   = lane & 3;
    const int q8   = lane >> 3;
    const int r8   = lane & 7;
    const int qrow0 = qt * 128;
    const int rw    = wid * 16;

    // ---- stage Q tile (half, coalesced uint4), then read A-fragments
    {
        const __half* qg = qkv + (size_t)(b * T_SEQ + qrow0) * C3 + h * HD;
        #pragma unroll
        for (int i = 0; i < 4; i++) {
            int f = tid + 256 * i;           // 1024 chunks: 128 rows x 8
            int row = f >> 3, c = f & 7;
            *(uint4*)(smc + SM_Q + row * 144 + c * 16) =
                *(const uint4*)(qg + (size_t)row * C3 + c * 8);
        }
    }
    __syncthreads();
    uint32_t qf[4][4];
    {
        const char* Qb = smc + SM_Q + (rw + g) * 144;
        #pragma unroll
        for (int ks = 0; ks < 4; ks++) {
            qf[ks][0] = *(const uint32_t*)(Qb + ks * 32 + tg * 4);
            qf[ks][1] = *(const uint32_t*)(Qb + 8 * 144 + ks * 32 + tg * 4);
            qf[ks][2] = *(const uint32_t*)(Qb + ks * 32 + tg * 4 + 16);
            qf[ks][3] = *(const uint32_t*)(Qb + 8 * 144 + ks * 32 + tg * 4 + 16);
        }
    }

    float o[8][4];
    #pragma unroll
    for (int nt = 0; nt < 8; nt++)
        #pragma unroll
        for (int e = 0; e < 4; e++) o[nt][e] = 0.0f;
    float m0 = -1e30f, m1 = -1e30f, l0 = 0.0f, l1 = 0.0f;
    const float scl2 = 0.125f * 1.44269504088896340736f;   // scale * log2(e)

    const int KT = 2 * qt + 2;
    const uint32_t vLane = (uint32_t)((r8 + (q8 & 1) * 8) * 144 + (q8 >> 1) * 16);

    auto issue = [&](int kt, int buf) {
        const __half* kb = qkv + (size_t)(b * T_SEQ + kt * 64) * C3 + C_EMB + h * HD;
        const __half* vb = kb + C_EMB;
        uint32_t kdst = sm32 + buf * SM_KV_STAGE;
        uint32_t vdst = kdst + SM_V0;
        #pragma unroll
        for (int i = 0; i < 2; i++) {
            int f = tid + 256 * i;           // 512 chunks: 64 rows x 8
            int row = f >> 3, c = f & 7;
            CP_ASYNC16(kdst + (uint32_t)(row * 144 + c * 16), kb + (size_t)row * C3 + c * 8);
        }
        #pragma unroll
        for (int i = 0; i < 2; i++) {
            int f = tid + 256 * i;
            int row = f >> 3, c = f & 7;
            CP_ASYNC16(vdst + (uint32_t)(row * 144 + c * 16), vb + (size_t)row * C3 + c * 8);
        }
        CP_COMMIT();
    };

    issue(0, 0);
    issue(1, 1);
    int buf = 0;
    for (int kt = 0; kt < KT; kt++) {
        if (kt + 1 < KT) CP_WAIT(1); else CP_WAIT(0);
        __syncthreads();                 // tile kt visible; kt-1 compute done
        if (kt + 2 < KT) {
            int nb = buf + 2; if (nb >= 3) nb -= 3;   // buffer of tile kt-1
            issue(kt + 2, nb);
        }

        const char* Kb = smc + buf * SM_KV_STAGE;
        const uint32_t vBase = sm32 + buf * SM_KV_STAGE + SM_V0;
        if (++buf == 3) buf = 0;

        bool alive = (kt * 64) <= (qrow0 + rw + 15);   // warp-uniform
        if (alive) {
            // ---- S = Q K^T  (16x64 per warp)
            float sa[8][4];
            #pragma unroll
            for (int nt = 0; nt < 8; nt++)
                #pragma unroll
                for (int e = 0; e < 4; e++) sa[nt][e] = 0.0f;
            #pragma unroll
            for (int ks = 0; ks < 4; ks++) {
                #pragma unroll
                for (int nt = 0; nt < 8; nt++) {
                    uint32_t bf[2];
                    const char* kp = Kb + (nt * 8 + g) * 144 + ks * 32 + tg * 4;
                    bf[0] = *(const uint32_t*)(kp);
                    bf[1] = *(const uint32_t*)(kp + 16);
                    mma_f16(sa[nt], qf[ks], bf);
                }
            }

            // ---- mask + online softmax in log2 domain (rows g and g+8)
            bool band = (kt * 64 + 63) > (qrow0 + rw);
            int grow0 = qrow0 + rw + g;
            int gcol0 = kt * 64 + 2 * tg;
            float mx0 = m0, mx1 = m1;
            #pragma unroll
            for (int nt = 0; nt < 8; nt++) {
                int c0 = gcol0 + nt * 8;
                float v0 = sa[nt][0] * scl2;
                float v1 = sa[nt][1] * scl2;
                float v2 = sa[nt][2] * scl2;
                float v3 = sa[nt][3] * scl2;
                if (band) {
                    if (c0     > grow0)     v0 = -1e30f;
                    if (c0 + 1 > grow0)     v1 = -1e30f;
                    if (c0     > grow0 + 8) v2 = -1e30f;
                    if (c0 + 1 > grow0 + 8) v3 = -1e30f;
                }
                sa[nt][0] = v0; sa[nt][1] = v1; sa[nt][2] = v2; sa[nt][3] = v3;
                mx0 = fmaxf(mx0, fmaxf(v0, v1));
                mx1 = fmaxf(mx1, fmaxf(v2, v3));
            }
            mx0 = fmaxf(mx0, __shfl_xor_sync(0xffffffffu, mx0, 1));
            mx0 = fmaxf(mx0, __shfl_xor_sync(0xffffffffu, mx0, 2));
            mx1 = fmaxf(mx1, __shfl_xor_sync(0xffffffffu, mx1, 1));
            mx1 = fmaxf(mx1, __shfl_xor_sync(0xffffffffu, mx1, 2));
            float corr0 = exp2f(m0 - mx0);
            float corr1 = exp2f(m1 - mx1);
            m0 = mx0; m1 = mx1;

            float ls0 = 0.0f, ls1 = 0.0f;
            #pragma unroll
            for (int nt = 0; nt < 8; nt++) {
                float p0 = exp2f(sa[nt][0] - m0);
                float p1 = exp2f(sa[nt][1] - m0);
                float p2 = exp2f(sa[nt][2] - m1);
                float p3 = exp2f(sa[nt][3] - m1);
                sa[nt][0] = p0; sa[nt][1] = p1; sa[nt][2] = p2; sa[nt][3] = p3;
                ls0 += p0 + p1;
                ls1 += p2 + p3;
            }
            l0 = l0 * corr0 + ls0;            // lane-partial; reduced at end
            l1 = l1 * corr1 + ls1;
            #pragma unroll
            for (int nt = 0; nt < 8; nt++) {
                o[nt][0] *= corr0; o[nt][1] *= corr0;
                o[nt][2] *= corr1; o[nt][3] *= corr1;
            }

            // ---- P register->register pack (S accum frag == A frag layout)
            uint32_t ph[8][2];
            #pragma unroll
            for (int nt = 0; nt < 8; nt++) {
                ph[nt][0] = packh2(sa[nt][0], sa[nt][1]);
                ph[nt][1] = packh2(sa[nt][2], sa[nt][3]);
            }

            // ---- O += P V  (V frags via ldmatrix.trans)
            #pragma unroll
            for (int ks = 0; ks < 4; ks++) {
                uint32_t pf[4] = { ph[2 * ks][0], ph[2 * ks][1],
                                   ph[2 * ks + 1][0], ph[2 * ks + 1][1] };
                #pragma unroll
                for (int j = 0; j < 4; j++) {
                    uint32_t t[4];
                    ldsm_x4_t(t, vBase + vLane + (uint32_t)(ks * (16 * 144) + j * 32));
                    uint32_t bA[2] = { t[0], t[1] };
                    uint32_t bB[2] = { t[2], t[3] };
                    mma_f16(o[2 * j], pf, bA);
                    mma_f16(o[2 * j + 1], pf, bB);
                }
            }
        }
    }

    // ---- final l reduction + normalize + write y (fp16 for proj GEMM)
    l0 += __shfl_xor_sync(0xffffffffu, l0, 1);
    l0 += __shfl_xor_sync(0xffffffffu, l0, 2);
    l1 += __shfl_xor_sync(0xffffffffu, l1, 1);
    l1 += __shfl_xor_sync(0xffffffffu, l1, 2);
    float inv0 = 1.0f / l0;
    float inv1 = 1.0f / l1;

    int row0 = b * T_SEQ + qrow0 + rw + g;
    __half2* Y = (__half2*)y;
    #pragma unroll
    for (int nt = 0; nt < 8; nt++) {
        int col = h * HD + nt * 8 + 2 * tg;
        Y[((size_t)row0 * C_EMB + col) >> 1] =
            __halves2half2(__float2half_rn(o[nt][0] * inv0), __float2half_rn(o[nt][1] * inv0));
        Y[((size_t)(row0 + 8) * C_EMB + col) >> 1] =
            __halves2half2(__float2half_rn(o[nt][2] * inv1), __float2half_rn(o[nt][3] * inv1));
    }
}

// ===========================================================================
extern "C" void kernel_launch(void* const* d_in, const int* in_sizes, int n_in,
                              void* d_out, int out_size)
{
    const float* x      = (const float*)d_in[0];
    const float* W_attn = (const float*)d_in[1];
    const float* b_attn = (const float*)d_in[2];
    const float* W_proj = (const float*)d_in[3];
    const float* b_proj = (const float*)d_in[4];
    float* out = (float*)d_out;

    __half *qkv, *yb, *xh, *wah, *wph;
    cudaGetSymbolAddress((void**)&qkv, g_qkv_h);
    cudaGetSymbolAddress((void**)&yb,  g_y_h);
    cudaGetSymbolAddress((void**)&xh,  g_xh);
    cudaGetSymbolAddress((void**)&wah, g_wah);
    cudaGetSymbolAddress((void**)&wph, g_wph);

    cudaFuncSetAttribute(gemm_f16_kernel,
                         cudaFuncAttributeMaxDynamicSharedMemorySize, GEMM_SMEM_BYTES);
    cudaFuncSetAttribute(attn_f16_kernel,
                         cudaFuncAttributeMaxDynamicSharedMemorySize, ATT_SMEM_BYTES);

    // 0) convert inputs to fp16 (RN) once
    {
        int n4x = (M_ROWS * C_EMB) / 4;
        int n4a = (C_EMB * C3) / 4;
        int n4p = (C_EMB * C_EMB) / 4;
        f32_to_f16_kernel<<<n4x / 256, 256>>>((const float4*)x, (__half2*)xh, n4x);
        f32_to_f16_kernel<<<n4a / 256, 256>>>((const float4*)W_attn, (__half2*)wah, n4a);
        f32_to_f16_kernel<<<n4p / 256, 256>>>((const float4*)W_proj, (__half2*)wph, n4p);
    }

    // 1) qkv = x_h @ Wa_h + b_attn   (fp32 accum, fp16 output)
    gemm_f16_kernel<<<dim3(C3 / BN, M_ROWS / BM), 256, GEMM_SMEM_BYTES>>>(
        xh, wah, b_attn, qkv, M_ROWS, C3, C_EMB, 1);

    // 2) causal flash attention -> y (fp16)
    attn_f16_kernel<<<dim3(T_SEQ / 128, NH, BATCH), 256, ATT_SMEM_BYTES>>>(qkv, yb);

    // 3) out = y @ Wp_h + b_proj  (fp32 output, not rounded)
    gemm_f16_kernel<<<dim3(C_EMB / BN, M_ROWS / BM), 256, GEMM_SMEM_BYTES>>>(
        yb, wph, b_proj, out, M_ROWS, C_EMB, C_EMB, 0);
}